// round 8
// baseline (speedup 1.0000x reference)
#include <cuda_runtime.h>
#include <cuda_bf16.h>
#include <math.h>

// ---------------------------------------------------------------------------
// TCAMSeeder: exact CUDA port of the JAX reference.
//   B=64 images of 512x512. Per image:
//     roi  = erode11x11( floor(cam*255) > th' )
//     n_fg = floor(0.3f * |roi|)
//     FG candidates = top n_fg ROI pixels by (cam+1e-8, idx asc)
//     FG seeds = top min(100,n_fg) candidates by log(v)+Gumbel(u_fg)
//     BG candidates = bottom 78643 pixels by (cam+1e-8, idx asc)
//     BG seeds = top 100 candidates by log(relu(1-v)+1e-8)+Gumbel(u_bg)
//   Both seed maps dilated 3x3; overlap -> ignore; out in {1,0,-255} (f32).
// All selections exact: 4096-bucket histogram + 64-bit radix refine of the
// boundary bucket (keys embed index for stable-sort / top_k tie semantics).
// ---------------------------------------------------------------------------

#define BN    64
#define HN    512
#define WN    512
#define HWN   262144
#define NBGC  78643
#define NBINS 4096
#define CAP   8192

typedef unsigned long long ull;
typedef unsigned int       u32;

// ------------------------------ device scratch ------------------------------
__device__ ull g_pre[BN][HN][8];    // pre-erosion roi bitmap
__device__ ull g_hb [BN][HN][8];    // horizontally eroded
__device__ ull g_er [BN][HN][8];    // fully eroded roi
__device__ u32 g_hist_all[BN][NBINS];
__device__ u32 g_hist_roi[BN][NBINS];
__device__ u32 g_hist_sf [BN][NBINS];
__device__ u32 g_hist_sb [BN][NBINS];
__device__ ull g_listB [BN][CAP];   // bg stage-1 boundary keys (flipped)
__device__ ull g_listF [BN][CAP];   // fg stage-1 boundary keys
__device__ ull g_listSF[BN][CAP];   // fg score boundary keys
__device__ ull g_listSB[BN][CAP];   // bg score boundary keys
__device__ int g_cntB[BN], g_cntF[BN], g_cntSF[BN], g_cntSB[BN];
__device__ u32 g_minb[BN], g_maxb[BN];
__device__ int g_cnt[BN], g_nfg[BN], g_deg[BN];
__device__ int g_Bb[BN], g_needB[BN];      // bg stage-1 boundary bucket / need
__device__ int g_Bf[BN], g_needF[BN];      // fg stage-1 boundary bucket / need
__device__ ull g_TbF[BN], g_Tf[BN];        // exact boundary thresholds
__device__ int g_Bsf[BN], g_needSf[BN], g_Bsb[BN], g_needSb[BN];
__device__ ull g_fgseed[BN][HN][8], g_bgseed[BN][HN][8];

// ------------------------------ helpers ------------------------------
__device__ __forceinline__ int vbucket(float v) {
    int k = (int)(v * 4096.0f);          // v > 0; monotone
    return k > (NBINS - 1) ? (NBINS - 1) : k;
}
__device__ __forceinline__ int sbucket(float s) {
    float t = (s + 40.0f) * 64.0f;       // valid scores land in (1100, 3800)
    int k = (int)t;
    if (k < 0) k = 0;
    if (k > NBINS - 1) k = NBINS - 1;
    return k;
}
__device__ __forceinline__ u32 fmono(float f) {
    u32 b = __float_as_uint(f);
    return (b & 0x80000000u) ? ~b : (b | 0x80000000u);
}

// exact m-th largest 64-bit key among list[0..cnt) (block-collective)
__device__ __forceinline__ ull radix_kth_largest(const ull* __restrict__ list,
                                                 int cnt, int need) {
    __shared__ u32 rh[256];
    __shared__ ull s_pref;
    __shared__ int s_nd;
    int tid = threadIdx.x;
    if (tid == 0) { s_pref = 0ull; s_nd = need; }
    __syncthreads();
    for (int by = 7; by >= 0; --by) {
        for (int j = tid; j < 256; j += blockDim.x) rh[j] = 0;
        __syncthreads();
        ull mask = (by == 7) ? 0ull : (~0ull << (8 * (by + 1)));
        ull pref = s_pref;
        for (int i = tid; i < cnt; i += blockDim.x) {
            ull k = list[i];
            if (((k ^ pref) & mask) == 0ull)
                atomicAdd(&rh[(int)((k >> (8 * by)) & 255ull)], 1u);
        }
        __syncthreads();
        if (tid == 0) {
            int nd = s_nd; long long cum = 0; int sel = 0;
            for (int v = 255; v >= 0; --v) {
                u32 c = rh[v];
                if (cum + (long long)c >= nd) { sel = v; s_nd = (int)(nd - cum); break; }
                cum += c;
            }
            s_pref = pref | (((ull)sel) << (8 * by));
        }
        __syncthreads();
    }
    return s_pref;
}

// ------------------------------ kernels ------------------------------

__global__ void k_zero() {
    int i = blockIdx.x * blockDim.x + threadIdx.x;
    int stride = gridDim.x * blockDim.x;
    for (int j = i; j < BN * NBINS; j += stride) {
        int b = j / NBINS, r = j % NBINS;
        g_hist_all[b][r] = 0; g_hist_roi[b][r] = 0;
        g_hist_sf[b][r]  = 0; g_hist_sb[b][r]  = 0;
    }
    ull* fs = &g_fgseed[0][0][0];
    ull* bs = &g_bgseed[0][0][0];
    for (int j = i; j < BN * HN * 8; j += stride) { fs[j] = 0ull; bs[j] = 0ull; }
    if (i < BN) {
        g_cntB[i] = 0; g_cntF[i] = 0; g_cntSF[i] = 0; g_cntSB[i] = 0;
        g_minb[i] = 0xFFFFFFFFu; g_maxb[i] = 0u;
    }
}

// pass over x: pre-erosion bitmap, min/max, all-pixel v-bucket histogram
__global__ void k_prep(const float* __restrict__ x, const float* __restrict__ rt) {
    __shared__ u32 sh[NBINS];
    int b = blockIdx.x >> 3;
    int chunk = blockIdx.x & 7;
    int tid = threadIdx.x;
    for (int j = tid; j < NBINS; j += 1024) sh[j] = 0;
    float th = rt[b];
    float thA = (th == 0.0f) ? 1.0f : ((th == 255.0f) ? 254.0f : th);
    u32 mn = 0xFFFFFFFFu, mx = 0u;
    const float* xb = x + (size_t)b * HWN;
    int base = chunk * 32768;
    __syncthreads();
    for (int i = 0; i < 32; i++) {
        int pix = base + i * 1024 + tid;
        float cam = xb[pix];
        u32 cb = __float_as_uint(cam);
        mn = min(mn, cb); mx = max(mx, cb);
        float v = cam + 1e-8f;
        atomicAdd(&sh[vbucket(v)], 1u);
        bool pred = floorf(cam * 255.0f) > thA;
        u32 bal = __ballot_sync(0xFFFFFFFFu, pred);
        if ((tid & 31) == 0)
            ((u32*)g_pre)[((size_t)b * HWN + (size_t)pix) >> 5] = bal;
    }
    __syncthreads();
    for (int j = tid; j < NBINS; j += 1024) {
        u32 c = sh[j];
        if (c) atomicAdd(&g_hist_all[b][j], c);
    }
    for (int o = 16; o; o >>= 1) {
        mn = min(mn, __shfl_down_sync(0xFFFFFFFFu, mn, o));
        mx = max(mx, __shfl_down_sync(0xFFFFFFFFu, mx, o));
    }
    __shared__ u32 smn[32], smx[32];
    if ((tid & 31) == 0) { smn[tid >> 5] = mn; smx[tid >> 5] = mx; }
    __syncthreads();
    if (tid < 32) {
        mn = smn[tid]; mx = smx[tid];
        for (int o = 16; o; o >>= 1) {
            mn = min(mn, __shfl_down_sync(0xFFFFFFFFu, mn, o));
            mx = max(mx, __shfl_down_sync(0xFFFFFFFFu, mx, o));
        }
        if (tid == 0) { atomicMin(&g_minb[b], mn); atomicMax(&g_maxb[b], mx); }
    }
}

// horizontal 11-wide erosion (OOB = 1, matches reduce_window init=+inf)
__global__ void k_erode_h() {
    int t = blockIdx.x * blockDim.x + threadIdx.x;
    if (t >= BN * HN) return;
    const ull* a = &g_pre[0][0][0] + (size_t)t * 8;
    ull av[8], r[8];
#pragma unroll
    for (int i = 0; i < 8; i++) { av[i] = a[i]; r[i] = av[i]; }
#pragma unroll
    for (int d = 1; d <= 5; d++) {
#pragma unroll
        for (int i = 0; i < 8; i++) {
            ull hi = (i < 7) ? av[i + 1] : ~0ull;
            ull lo = (i > 0) ? av[i - 1] : ~0ull;
            ull rs = (av[i] >> d) | (hi << (64 - d));
            ull ls = (av[i] << d) | (lo >> (64 - d));
            r[i] &= rs & ls;
        }
    }
    ull* o = &g_hb[0][0][0] + (size_t)t * 8;
#pragma unroll
    for (int i = 0; i < 8; i++) o[i] = r[i];
}

// vertical 11-tall erosion (OOB = 1)
__global__ void k_erode_v() {
    int t = blockIdx.x * blockDim.x + threadIdx.x;
    if (t >= BN * HN * 8) return;
    int b = t >> 12;
    int rem = t & 4095;
    int row = rem >> 3;
    int w = rem & 7;
    ull r = ~0ull;
#pragma unroll
    for (int d = -5; d <= 5; d++) {
        int rr = row + d;
        if (rr >= 0 && rr < HN) r &= g_hb[b][rr][w];
    }
    g_er[b][row][w] = r;
}

__global__ void k_count() {
    __shared__ int ss[256];
    int b = blockIdx.x, tid = threadIdx.x;
    const ull* e = &g_er[b][0][0];
    int s = 0;
    for (int j = tid; j < HN * 8; j += 256) s += __popcll(e[j]);
    ss[tid] = s;
    __syncthreads();
    for (int o = 128; o; o >>= 1) {
        if (tid < o) ss[tid] += ss[tid + o];
        __syncthreads();
    }
    if (tid == 0) {
        int n = ss[0];
        g_cnt[b] = n;
        g_nfg[b] = (int)floorf(0.3f * (float)n);
        g_deg[b] = (g_minb[b] == g_maxb[b]) ? 1 : 0;
    }
}

__global__ void k_scanAll() {
    int b = blockIdx.x;
    if (threadIdx.x) return;
    long long cum = 0;
    for (int j = 0; j < NBINS; j++) {
        u32 c = g_hist_all[b][j];
        if (cum + (long long)c >= NBGC) { g_Bb[b] = j; g_needB[b] = (int)(NBGC - cum); return; }
        cum += c;
    }
    g_Bb[b] = NBINS; g_needB[b] = 0;
}

// pass over x: roi v-bucket histogram + collect bg boundary keys
__global__ void k_roiHistCollectB(const float* __restrict__ x) {
    __shared__ u32 sh[NBINS];
    int b = blockIdx.x >> 3;
    int chunk = blockIdx.x & 7;
    int tid = threadIdx.x;
    for (int j = tid; j < NBINS; j += 1024) sh[j] = 0;
    int Bb = g_Bb[b];
    const float* xb = x + (size_t)b * HWN;
    int base = chunk * 32768;
    __syncthreads();
    for (int i = 0; i < 32; i++) {
        int pix = base + i * 1024 + tid;
        float cam = xb[pix];
        float v = cam + 1e-8f;
        u32 vbits = __float_as_uint(v);
        int vb = vbucket(v);
        u32 ew = ((const u32*)g_er)[((size_t)b * HWN + (size_t)pix) >> 5];
        int roi = (ew >> (pix & 31)) & 1;
        if (roi) atomicAdd(&sh[vb], 1u);
        if (vb == Bb) {
            int pos = atomicAdd(&g_cntB[b], 1);
            if (pos < CAP)
                g_listB[b][pos] = ~((((ull)vbits) << 32) | (u32)pix);
        }
    }
    __syncthreads();
    for (int j = tid; j < NBINS; j += 1024) {
        u32 c = sh[j];
        if (c) atomicAdd(&g_hist_roi[b][j], c);
    }
}

__global__ void k_scanRoi() {
    int b = blockIdx.x;
    if (threadIdx.x) return;
    int n = g_nfg[b];
    if (n <= 0) { g_Bf[b] = NBINS; g_needF[b] = 0; return; }
    long long cum = 0;
    for (int j = NBINS - 1; j >= 0; j--) {
        u32 c = g_hist_roi[b][j];
        if (cum + (long long)c >= n) { g_Bf[b] = j; g_needF[b] = (int)(n - cum); return; }
        cum += c;
    }
    g_Bf[b] = NBINS; g_needF[b] = 0;
}

// pass over x: collect fg boundary keys
__global__ void k_collectF(const float* __restrict__ x) {
    int b = blockIdx.x >> 3;
    int Bf = g_Bf[b];
    if (Bf >= NBINS) return;
    int chunk = blockIdx.x & 7;
    int tid = threadIdx.x;
    const float* xb = x + (size_t)b * HWN;
    int base = chunk * 32768;
    for (int i = 0; i < 32; i++) {
        int pix = base + i * 1024 + tid;
        float cam = xb[pix];
        float v = cam + 1e-8f;
        int vb = vbucket(v);
        if (vb != Bf) continue;
        u32 ew = ((const u32*)g_er)[((size_t)b * HWN + (size_t)pix) >> 5];
        if (!((ew >> (pix & 31)) & 1)) continue;
        u32 vbits = __float_as_uint(v);
        int pos = atomicAdd(&g_cntF[b], 1);
        if (pos < CAP)
            g_listF[b][pos] = (((ull)vbits) << 32) | (u32)(HWN - 1 - pix);
    }
}

__global__ void k_refine1() {
    int b = blockIdx.x, which = blockIdx.y;  // 0 = bg (flipped keys), 1 = fg
    int cnt = which ? g_cntF[b] : g_cntB[b];
    if (cnt > CAP) cnt = CAP;
    int need = which ? g_needF[b] : g_needB[b];
    if (need <= 0) {
        if (threadIdx.x == 0) { if (which) g_Tf[b] = ~0ull; else g_TbF[b] = ~0ull; }
        return;
    }
    const ull* list = which ? g_listF[b] : g_listB[b];
    ull T = radix_kth_largest(list, cnt, need);
    if (threadIdx.x == 0) { if (which) g_Tf[b] = T; else g_TbF[b] = T; }
}

__device__ __forceinline__ bool bg_cand(int vb, u32 vbits, int pix, int Bb, ull TbF) {
    if (vb < Bb) return true;
    if (vb != Bb) return false;
    return (~((((ull)vbits) << 32) | (u32)pix)) >= TbF;
}
__device__ __forceinline__ bool fg_cand(int roi, int vb, u32 vbits, int pix, int Bf, ull Tf) {
    if (!roi) return false;
    if (vb > Bf) return true;
    if (vb != Bf) return false;
    return ((((ull)vbits) << 32) | (u32)(HWN - 1 - pix)) >= Tf;
}

// pass over x,u: score histograms for fg and bg candidates
__global__ void k_scoreHist(const float* __restrict__ x,
                            const float* __restrict__ ufg,
                            const float* __restrict__ ubg) {
    __shared__ u32 shf[NBINS];
    __shared__ u32 shb[NBINS];
    int b = blockIdx.x >> 3;
    int chunk = blockIdx.x & 7;
    int tid = threadIdx.x;
    for (int j = tid; j < NBINS; j += 1024) { shf[j] = 0; shb[j] = 0; }
    int Bb = g_Bb[b], Bf = g_Bf[b];
    ull TbF = g_TbF[b], Tf = g_Tf[b];
    const float* xb = x + (size_t)b * HWN;
    const float* uf = ufg + (size_t)b * HWN;
    const float* ub = ubg + (size_t)b * HWN;
    int base = chunk * 32768;
    __syncthreads();
    for (int i = 0; i < 32; i++) {
        int pix = base + i * 1024 + tid;
        float cam = xb[pix];
        float v = cam + 1e-8f;
        u32 vbits = __float_as_uint(v);
        int vb = vbucket(v);
        u32 ew = ((const u32*)g_er)[((size_t)b * HWN + (size_t)pix) >> 5];
        int roi = (ew >> (pix & 31)) & 1;
        if (bg_cand(vb, vbits, pix, Bb, TbF)) {
            float u = ub[pix];
            float pv = fmaxf(1.0f - v, 0.0f) + 1e-8f;
            float s = logf(pv) - logf(-logf(u));
            atomicAdd(&shb[sbucket(s)], 1u);
        }
        if (fg_cand(roi, vb, vbits, pix, Bf, Tf)) {
            float u = uf[pix];
            float s = logf(v) - logf(-logf(u));
            atomicAdd(&shf[sbucket(s)], 1u);
        }
    }
    __syncthreads();
    for (int j = tid; j < NBINS; j += 1024) {
        u32 c = shf[j]; if (c) atomicAdd(&g_hist_sf[b][j], c);
        u32 d = shb[j]; if (d) atomicAdd(&g_hist_sb[b][j], d);
    }
}

__global__ void k_scanScores() {
    int b = blockIdx.x, which = blockIdx.y;  // 0 = fg, 1 = bg
    if (threadIdx.x) return;
    int K;
    const u32* hist;
    if (which == 0) {
        int nfg = g_nfg[b];
        K = g_deg[b] ? 0 : (nfg < 100 ? nfg : 100);
        hist = g_hist_sf[b];
    } else {
        K = g_deg[b] ? 0 : 100;
        hist = g_hist_sb[b];
    }
    int Bs = NBINS, need = 0;
    if (K > 0) {
        long long cum = 0;
        for (int j = NBINS - 1; j >= 0; j--) {
            u32 c = hist[j];
            if (cum + (long long)c >= K) { Bs = j; need = (int)(K - cum); break; }
            cum += c;
        }
    }
    if (which == 0) { g_Bsf[b] = Bs; g_needSf[b] = need; }
    else            { g_Bsb[b] = Bs; g_needSb[b] = need; }
}

__device__ __forceinline__ void mark_seed(ull* seedbase, int b, int pix) {
    int row = pix >> 9, col = pix & 511;
    atomicOr(&seedbase[(size_t)b * HN * 8 + (size_t)row * 8 + (col >> 6)],
             1ull << (col & 63));
}

// pass over x,u: mark sure seeds, collect score boundary keys
__global__ void k_scorePass2(const float* __restrict__ x,
                             const float* __restrict__ ufg,
                             const float* __restrict__ ubg) {
    int b = blockIdx.x >> 3;
    int chunk = blockIdx.x & 7;
    int tid = threadIdx.x;
    int Bb = g_Bb[b], Bf = g_Bf[b];
    ull TbF = g_TbF[b], Tf = g_Tf[b];
    int Bsf = g_Bsf[b], Bsb = g_Bsb[b];
    const float* xb = x + (size_t)b * HWN;
    const float* uf = ufg + (size_t)b * HWN;
    const float* ub = ubg + (size_t)b * HWN;
    int base = chunk * 32768;
    for (int i = 0; i < 32; i++) {
        int pix = base + i * 1024 + tid;
        float cam = xb[pix];
        float v = cam + 1e-8f;
        u32 vbits = __float_as_uint(v);
        int vb = vbucket(v);
        u32 ew = ((const u32*)g_er)[((size_t)b * HWN + (size_t)pix) >> 5];
        int roi = (ew >> (pix & 31)) & 1;
        if (bg_cand(vb, vbits, pix, Bb, TbF)) {
            float u = ub[pix];
            float pv = fmaxf(1.0f - v, 0.0f) + 1e-8f;
            float s = logf(pv) - logf(-logf(u));
            int sb = sbucket(s);
            if (sb > Bsb) {
                mark_seed(&g_bgseed[0][0][0], b, pix);
            } else if (sb == Bsb) {
                int pos = atomicAdd(&g_cntSB[b], 1);
                if (pos < CAP)
                    g_listSB[b][pos] = (((ull)fmono(s)) << 32) | (u32)(HWN - 1 - pix);
            }
        }
        if (fg_cand(roi, vb, vbits, pix, Bf, Tf)) {
            float u = uf[pix];
            float s = logf(v) - logf(-logf(u));
            int sb = sbucket(s);
            if (sb > Bsf) {
                mark_seed(&g_fgseed[0][0][0], b, pix);
            } else if (sb == Bsf) {
                int pos = atomicAdd(&g_cntSF[b], 1);
                if (pos < CAP)
                    g_listSF[b][pos] = (((ull)fmono(s)) << 32) | (u32)(HWN - 1 - pix);
            }
        }
    }
}

__global__ void k_refineScores() {
    int b = blockIdx.x, which = blockIdx.y;  // 0 = fg, 1 = bg
    int cnt = which ? g_cntSB[b] : g_cntSF[b];
    if (cnt > CAP) cnt = CAP;
    int need = which ? g_needSb[b] : g_needSf[b];
    if (need <= 0) return;
    const ull* list = which ? g_listSB[b] : g_listSF[b];
    ull T = radix_kth_largest(list, cnt, need);
    ull* seed = which ? &g_bgseed[0][0][0] : &g_fgseed[0][0][0];
    for (int i = threadIdx.x; i < cnt; i += blockDim.x) {
        ull k = list[i];
        if (k >= T) {
            int pix = (int)((u32)(HWN - 1) - (u32)(k & 0xFFFFFFFFull));
            mark_seed(seed, b, pix);
        }
    }
}

// 3x3 dilation of both seed maps + compose float32 output
__global__ void k_output(float* __restrict__ out) {
    __shared__ ull sv[2][8];
    __shared__ ull sh2[2][8];
    int t = blockIdx.x;
    int b = t >> 9;
    int row = t & 511;
    int c = threadIdx.x;
    if (c < 16) {
        int q = c >> 3, w = c & 7;
        const ull* seed = q ? &g_bgseed[0][0][0] : &g_fgseed[0][0][0];
        size_t basei = (size_t)b * HN * 8;
        ull v = seed[basei + (size_t)row * 8 + w];
        if (row > 0)      v |= seed[basei + (size_t)(row - 1) * 8 + w];
        if (row < HN - 1) v |= seed[basei + (size_t)(row + 1) * 8 + w];
        sv[q][w] = v;
    }
    __syncthreads();
    if (c < 16) {
        int q = c >> 3, w = c & 7;
        ull m = sv[q][w];
        ull hh = m | (m << 1) | (m >> 1);
        if (w > 0) hh |= sv[q][w - 1] >> 63;
        if (w < 7) hh |= sv[q][w + 1] << 63;
        sh2[q][w] = hh;
    }
    __syncthreads();
    int w = c >> 6, bit = c & 63;
    int f = (int)((sh2[0][w] >> bit) & 1ull);
    int g = (int)((sh2[1][w] >> bit) & 1ull);
    float val;
    if (f && !g)      val = 1.0f;
    else if (g && !f) val = 0.0f;
    else              val = -255.0f;
    out[(size_t)b * HWN + (size_t)row * WN + c] = val;
}

// ------------------------------ launch ------------------------------
extern "C" void kernel_launch(void* const* d_in, const int* in_sizes, int n_in,
                              void* d_out, int out_size) {
    (void)out_size;
    // Defensive input mapping: roi_thresh is the only 64-element input; the
    // three HWN*BN-sized inputs keep their metadata relative order (x, u_fg, u_bg).
    const float* big[3] = {nullptr, nullptr, nullptr};
    const float* rt = nullptr;
    int nb = 0;
    for (int i = 0; i < n_in && i < 4; i++) {
        if (in_sizes[i] == BN) rt = (const float*)d_in[i];
        else if (nb < 3)       big[nb++] = (const float*)d_in[i];
    }
    const float* x   = big[0];
    const float* ufg = big[1];
    const float* ubg = big[2];
    float* out = (float*)d_out;

    k_zero<<<1024, 256>>>();
    k_prep<<<BN * 8, 1024>>>(x, rt);
    k_erode_h<<<(BN * HN + 255) / 256, 256>>>();
    k_erode_v<<<(BN * HN * 8 + 255) / 256, 256>>>();
    k_count<<<BN, 256>>>();
    k_scanAll<<<BN, 32>>>();
    k_roiHistCollectB<<<BN * 8, 1024>>>(x);
    k_scanRoi<<<BN, 32>>>();
    k_collectF<<<BN * 8, 1024>>>(x);
    k_refine1<<<dim3(BN, 2), 256>>>();
    k_scoreHist<<<BN * 8, 1024>>>(x, ufg, ubg);
    k_scanScores<<<dim3(BN, 2), 32>>>();
    k_scorePass2<<<BN * 8, 1024>>>(x, ufg, ubg);
    k_refineScores<<<dim3(BN, 2), 256>>>();
    k_output<<<BN * HN, 512>>>(out);
}

// round 9
// speedup vs baseline: 1.4953x; 1.4953x over previous
#include <cuda_runtime.h>
#include <cuda_bf16.h>
#include <math.h>

// ---------------------------------------------------------------------------
// TCAMSeeder: exact CUDA port of the JAX reference (see earlier rounds).
// R9: parallel bucket scans (was serial 1-thread L2-latency-bound loops),
//     candidate score-key compaction (drops the 192MB second score pass),
//     count fused into erosion.
// ---------------------------------------------------------------------------

#define BN    64
#define HN    512
#define WN    512
#define HWN   262144
#define NBGC  78643
#define NBINS 4096
#define CAP   8192
#define CAPC  78848

typedef unsigned long long ull;
typedef unsigned int       u32;

// ------------------------------ device scratch ------------------------------
__device__ ull g_pre[BN][HN][8];    // pre-erosion roi bitmap
__device__ ull g_hb [BN][HN][8];    // horizontally eroded
__device__ ull g_er [BN][HN][8];    // fully eroded roi
__device__ u32 g_hist_all[BN][NBINS];
__device__ u32 g_hist_roi[BN][NBINS];
__device__ u32 g_hist_sf [BN][NBINS];
__device__ u32 g_hist_sb [BN][NBINS];
__device__ ull g_listB [BN][CAP];   // bg stage-1 boundary keys (flipped)
__device__ ull g_listF [BN][CAP];   // fg stage-1 boundary keys
__device__ ull g_listSF[BN][CAP];   // fg score boundary keys
__device__ ull g_listSB[BN][CAP];   // bg score boundary keys
__device__ ull g_keyF[BN][CAPC];    // compacted fg candidate score keys
__device__ ull g_keyB[BN][CAPC];    // compacted bg candidate score keys
__device__ int g_nF[BN], g_nB[BN];
__device__ int g_cntB[BN], g_cntF[BN], g_cntSF[BN], g_cntSB[BN];
__device__ u32 g_minb[BN], g_maxb[BN];
__device__ int g_cnt[BN], g_nfg[BN], g_deg[BN];
__device__ int g_Bb[BN], g_needB[BN];      // bg stage-1 boundary bucket / need
__device__ int g_Bf[BN], g_needF[BN];      // fg stage-1 boundary bucket / need
__device__ ull g_TbF[BN], g_Tf[BN];        // exact stage-1 thresholds
__device__ int g_Bsf[BN], g_needSf[BN], g_Bsb[BN], g_needSb[BN];
__device__ ull g_fgseed[BN][HN][8], g_bgseed[BN][HN][8];

// ------------------------------ helpers ------------------------------
__device__ __forceinline__ int vbucket(float v) {
    int k = (int)(v * 4096.0f);
    return k > (NBINS - 1) ? (NBINS - 1) : k;
}
__device__ __forceinline__ int sbucket(float s) {
    float t = (s + 40.0f) * 64.0f;
    int k = (int)t;
    if (k < 0) k = 0;
    if (k > NBINS - 1) k = NBINS - 1;
    return k;
}
__device__ __forceinline__ u32 fmono(float f) {
    u32 b = __float_as_uint(f);
    return (b & 0x80000000u) ? ~b : (b | 0x80000000u);
}
__device__ __forceinline__ float fmono_inv(u32 m) {
    u32 b = (m & 0x80000000u) ? (m ^ 0x80000000u) : ~m;
    return __uint_as_float(b);
}

// exact m-th largest 64-bit key among list[0..cnt) (block-collective)
__device__ __forceinline__ ull radix_kth_largest(const ull* __restrict__ list,
                                                 int cnt, int need) {
    __shared__ u32 rh[256];
    __shared__ ull s_pref;
    __shared__ int s_nd;
    int tid = threadIdx.x;
    if (tid == 0) { s_pref = 0ull; s_nd = need; }
    __syncthreads();
    for (int by = 7; by >= 0; --by) {
        for (int j = tid; j < 256; j += blockDim.x) rh[j] = 0;
        __syncthreads();
        ull mask = (by == 7) ? 0ull : (~0ull << (8 * (by + 1)));
        ull pref = s_pref;
        for (int i = tid; i < cnt; i += blockDim.x) {
            ull k = list[i];
            if (((k ^ pref) & mask) == 0ull)
                atomicAdd(&rh[(int)((k >> (8 * by)) & 255ull)], 1u);
        }
        __syncthreads();
        if (tid == 0) {
            int nd = s_nd; long long cum = 0; int sel = 0;
            for (int v = 255; v >= 0; --v) {
                u32 c = rh[v];
                if (cum + (long long)c >= nd) { sel = v; s_nd = (int)(nd - cum); break; }
                cum += c;
            }
            s_pref = pref | (((ull)sel) << (8 * by));
        }
        __syncthreads();
    }
    return s_pref;
}

// parallel crossing search over 4096-bin histogram (256-thread block).
// ascending: smallest j with cumsum_{0..j} >= K; descending: from the top.
// res[0]=bucket (NBINS if none/K<=0), res[1]=K - cum_before.
__device__ __forceinline__ void find_bucket_256(const u32* __restrict__ hist,
                                                int K, bool ascending,
                                                int* res) {
    __shared__ u32 wsum[8];
    int tid = threadIdx.x;
    u32 local[16];
    u32 sum = 0;
#pragma unroll
    for (int i = 0; i < 16; i++) {
        int j = tid * 16 + i;
        int jj = ascending ? j : (NBINS - 1 - j);
        local[i] = hist[jj];
        sum += local[i];
    }
    u32 inc = sum;
#pragma unroll
    for (int o = 1; o < 32; o <<= 1) {
        u32 v = __shfl_up_sync(0xFFFFFFFFu, inc, o);
        if ((tid & 31) >= o) inc += v;
    }
    if ((tid & 31) == 31) wsum[tid >> 5] = inc;
    if (tid == 0) { res[0] = NBINS; res[1] = 0; }
    __syncthreads();
    int w = tid >> 5;
    u32 wbase = 0;
#pragma unroll
    for (int k = 0; k < 8; k++) wbase += (k < w) ? wsum[k] : 0u;
    u32 cum = wbase + inc - sum;     // exclusive prefix before this thread's bins
    if (K > 0) {
#pragma unroll
        for (int i = 0; i < 16; i++) {
            u32 c = local[i];
            if ((int)cum < K && (int)(cum + c) >= K) {
                int j = tid * 16 + i;
                res[0] = ascending ? j : (NBINS - 1 - j);
                res[1] = K - (int)cum;
            }
            cum += c;
        }
    }
    __syncthreads();
}

// warp-aggregated list append; returns slot or -1
__device__ __forceinline__ int warp_append(int* counter, bool pred) {
    int lane = threadIdx.x & 31;
    u32 m = __ballot_sync(0xFFFFFFFFu, pred);
    int n = __popc(m);
    int pos = -1;
    if (n) {
        int leader = __ffs(m) - 1;
        int base = 0;
        if (lane == leader) base = atomicAdd(counter, n);
        base = __shfl_sync(0xFFFFFFFFu, base, leader);
        if (pred) pos = base + __popc(m & ((1u << lane) - 1u));
    }
    return pos;
}

// ------------------------------ kernels ------------------------------

__global__ void k_zero() {
    int i = blockIdx.x * blockDim.x + threadIdx.x;
    int stride = gridDim.x * blockDim.x;
    for (int j = i; j < BN * NBINS; j += stride) {
        int b = j / NBINS, r = j % NBINS;
        g_hist_all[b][r] = 0; g_hist_roi[b][r] = 0;
        g_hist_sf[b][r]  = 0; g_hist_sb[b][r]  = 0;
    }
    ull* fs = &g_fgseed[0][0][0];
    ull* bs = &g_bgseed[0][0][0];
    for (int j = i; j < BN * HN * 8; j += stride) { fs[j] = 0ull; bs[j] = 0ull; }
    if (i < BN) {
        g_cntB[i] = 0; g_cntF[i] = 0; g_cntSF[i] = 0; g_cntSB[i] = 0;
        g_nF[i] = 0; g_nB[i] = 0; g_cnt[i] = 0;
        g_minb[i] = 0xFFFFFFFFu; g_maxb[i] = 0u;
    }
}

// pass over x: pre-erosion bitmap, min/max, all-pixel v-bucket histogram
__global__ void k_prep(const float* __restrict__ x, const float* __restrict__ rt) {
    __shared__ u32 sh[NBINS];
    int b = blockIdx.x >> 3;
    int chunk = blockIdx.x & 7;
    int tid = threadIdx.x;
    for (int j = tid; j < NBINS; j += 1024) sh[j] = 0;
    float th = rt[b];
    float thA = (th == 0.0f) ? 1.0f : ((th == 255.0f) ? 254.0f : th);
    u32 mn = 0xFFFFFFFFu, mx = 0u;
    const float* xb = x + (size_t)b * HWN;
    int base = chunk * 32768;
    __syncthreads();
    for (int i = 0; i < 32; i++) {
        int pix = base + i * 1024 + tid;
        float cam = xb[pix];
        u32 cb = __float_as_uint(cam);
        mn = min(mn, cb); mx = max(mx, cb);
        float v = cam + 1e-8f;
        atomicAdd(&sh[vbucket(v)], 1u);
        bool pred = floorf(cam * 255.0f) > thA;
        u32 bal = __ballot_sync(0xFFFFFFFFu, pred);
        if ((tid & 31) == 0)
            ((u32*)g_pre)[((size_t)b * HWN + (size_t)pix) >> 5] = bal;
    }
    __syncthreads();
    for (int j = tid; j < NBINS; j += 1024) {
        u32 c = sh[j];
        if (c) atomicAdd(&g_hist_all[b][j], c);
    }
    for (int o = 16; o; o >>= 1) {
        mn = min(mn, __shfl_down_sync(0xFFFFFFFFu, mn, o));
        mx = max(mx, __shfl_down_sync(0xFFFFFFFFu, mx, o));
    }
    __shared__ u32 smn[32], smx[32];
    if ((tid & 31) == 0) { smn[tid >> 5] = mn; smx[tid >> 5] = mx; }
    __syncthreads();
    if (tid < 32) {
        mn = smn[tid]; mx = smx[tid];
        for (int o = 16; o; o >>= 1) {
            mn = min(mn, __shfl_down_sync(0xFFFFFFFFu, mn, o));
            mx = max(mx, __shfl_down_sync(0xFFFFFFFFu, mx, o));
        }
        if (tid == 0) { atomicMin(&g_minb[b], mn); atomicMax(&g_maxb[b], mx); }
    }
}

// horizontal 11-wide erosion (OOB = 1)
__global__ void k_erode_h() {
    int t = blockIdx.x * blockDim.x + threadIdx.x;
    if (t >= BN * HN) return;
    const ull* a = &g_pre[0][0][0] + (size_t)t * 8;
    ull av[8], r[8];
#pragma unroll
    for (int i = 0; i < 8; i++) { av[i] = a[i]; r[i] = av[i]; }
#pragma unroll
    for (int d = 1; d <= 5; d++) {
#pragma unroll
        for (int i = 0; i < 8; i++) {
            ull hi = (i < 7) ? av[i + 1] : ~0ull;
            ull lo = (i > 0) ? av[i - 1] : ~0ull;
            ull rs = (av[i] >> d) | (hi << (64 - d));
            ull ls = (av[i] << d) | (lo >> (64 - d));
            r[i] &= rs & ls;
        }
    }
    ull* o = &g_hb[0][0][0] + (size_t)t * 8;
#pragma unroll
    for (int i = 0; i < 8; i++) o[i] = r[i];
}

// vertical 11-tall erosion (OOB = 1) + fused roi popcount
__global__ void k_erode_v() {
    int t = blockIdx.x * blockDim.x + threadIdx.x;
    int b = t >> 12;
    int rem = t & 4095;
    int row = rem >> 3;
    int w = rem & 7;
    ull r = ~0ull;
#pragma unroll
    for (int d = -5; d <= 5; d++) {
        int rr = row + d;
        if (rr >= 0 && rr < HN) r &= g_hb[b][rr][w];
    }
    g_er[b][row][w] = r;
    int pc = __popcll(r);
    for (int o = 16; o; o >>= 1) pc += __shfl_down_sync(0xFFFFFFFFu, pc, o);
    if ((threadIdx.x & 31) == 0) atomicAdd(&g_cnt[b], pc);
}

// parallel bg stage-1 scan + n_fg/deg
__global__ void k_scanBG() {
    __shared__ int res[2];
    int b = blockIdx.x;
    find_bucket_256(g_hist_all[b], NBGC, true, res);
    if (threadIdx.x == 0) {
        g_Bb[b] = res[0]; g_needB[b] = res[1];
        g_nfg[b] = (int)floorf(0.3f * (float)g_cnt[b]);
        g_deg[b] = (g_minb[b] == g_maxb[b]) ? 1 : 0;
    }
}

// pass over x: roi v-bucket histogram + collect bg boundary keys
__global__ void k_roiHistCollectB(const float* __restrict__ x) {
    __shared__ u32 sh[NBINS];
    int b = blockIdx.x >> 3;
    int chunk = blockIdx.x & 7;
    int tid = threadIdx.x;
    for (int j = tid; j < NBINS; j += 1024) sh[j] = 0;
    int Bb = g_Bb[b];
    const float* xb = x + (size_t)b * HWN;
    int base = chunk * 32768;
    __syncthreads();
    for (int i = 0; i < 32; i++) {
        int pix = base + i * 1024 + tid;
        float cam = xb[pix];
        float v = cam + 1e-8f;
        u32 vbits = __float_as_uint(v);
        int vb = vbucket(v);
        u32 ew = ((const u32*)g_er)[((size_t)b * HWN + (size_t)pix) >> 5];
        int roi = (ew >> (pix & 31)) & 1;
        if (roi) atomicAdd(&sh[vb], 1u);
        int pos = warp_append(&g_cntB[b], vb == Bb);
        if (pos >= 0 && pos < CAP)
            g_listB[b][pos] = ~((((ull)vbits) << 32) | (u32)pix);
    }
    __syncthreads();
    for (int j = tid; j < NBINS; j += 1024) {
        u32 c = sh[j];
        if (c) atomicAdd(&g_hist_roi[b][j], c);
    }
}

// parallel fg stage-1 scan
__global__ void k_scanFG() {
    __shared__ int res[2];
    int b = blockIdx.x;
    find_bucket_256(g_hist_roi[b], g_nfg[b], false, res);
    if (threadIdx.x == 0) { g_Bf[b] = res[0]; g_needF[b] = res[1]; }
}

// pass over x: collect fg boundary keys
__global__ void k_collectF(const float* __restrict__ x) {
    int b = blockIdx.x >> 3;
    int Bf = g_Bf[b];
    if (Bf >= NBINS) return;
    int chunk = blockIdx.x & 7;
    int tid = threadIdx.x;
    const float* xb = x + (size_t)b * HWN;
    int base = chunk * 32768;
    for (int i = 0; i < 32; i++) {
        int pix = base + i * 1024 + tid;
        float cam = xb[pix];
        float v = cam + 1e-8f;
        int vb = vbucket(v);
        u32 ew = ((const u32*)g_er)[((size_t)b * HWN + (size_t)pix) >> 5];
        int roi = (ew >> (pix & 31)) & 1;
        bool pred = roi && (vb == Bf);
        u32 vbits = __float_as_uint(v);
        int pos = warp_append(&g_cntF[b], pred);
        if (pos >= 0 && pos < CAP)
            g_listF[b][pos] = (((ull)vbits) << 32) | (u32)(HWN - 1 - pix);
    }
}

__global__ void k_refine1() {
    int b = blockIdx.x, which = blockIdx.y;  // 0 = bg (flipped keys), 1 = fg
    int cnt = which ? g_cntF[b] : g_cntB[b];
    if (cnt > CAP) cnt = CAP;
    int need = which ? g_needF[b] : g_needB[b];
    if (need <= 0) {
        if (threadIdx.x == 0) { if (which) g_Tf[b] = ~0ull; else g_TbF[b] = ~0ull; }
        return;
    }
    const ull* list = which ? g_listF[b] : g_listB[b];
    ull T = radix_kth_largest(list, cnt, need);
    if (threadIdx.x == 0) { if (which) g_Tf[b] = T; else g_TbF[b] = T; }
}

__device__ __forceinline__ bool bg_cand(int vb, u32 vbits, int pix, int Bb, ull TbF) {
    if (vb < Bb) return true;
    if (vb != Bb) return false;
    return (~((((ull)vbits) << 32) | (u32)pix)) >= TbF;
}
__device__ __forceinline__ bool fg_cand(int roi, int vb, u32 vbits, int pix, int Bf, ull Tf) {
    if (!roi) return false;
    if (vb > Bf) return true;
    if (vb != Bf) return false;
    return ((((ull)vbits) << 32) | (u32)(HWN - 1 - pix)) >= Tf;
}

// pass over x,u: score histograms + compact candidate score keys
__global__ void k_scoreCompact(const float* __restrict__ x,
                               const float* __restrict__ ufg,
                               const float* __restrict__ ubg) {
    __shared__ u32 shf[NBINS];
    __shared__ u32 shb[NBINS];
    int b = blockIdx.x >> 3;
    int chunk = blockIdx.x & 7;
    int tid = threadIdx.x;
    for (int j = tid; j < NBINS; j += 1024) { shf[j] = 0; shb[j] = 0; }
    int Bb = g_Bb[b], Bf = g_Bf[b];
    ull TbF = g_TbF[b], Tf = g_Tf[b];
    const float* xb = x + (size_t)b * HWN;
    const float* uf = ufg + (size_t)b * HWN;
    const float* ub = ubg + (size_t)b * HWN;
    int base = chunk * 32768;
    __syncthreads();
    for (int i = 0; i < 32; i++) {
        int pix = base + i * 1024 + tid;
        float cam = xb[pix];
        float v = cam + 1e-8f;
        u32 vbits = __float_as_uint(v);
        int vb = vbucket(v);
        u32 ew = ((const u32*)g_er)[((size_t)b * HWN + (size_t)pix) >> 5];
        int roi = (ew >> (pix & 31)) & 1;

        bool isb = bg_cand(vb, vbits, pix, Bb, TbF);
        ull keyb = 0;
        if (isb) {
            float u = ub[pix];
            float pv = fmaxf(1.0f - v, 0.0f) + 1e-8f;
            float s = logf(pv) - logf(-logf(u));
            atomicAdd(&shb[sbucket(s)], 1u);
            keyb = (((ull)fmono(s)) << 32) | (u32)(HWN - 1 - pix);
        }
        int posb = warp_append(&g_nB[b], isb);
        if (posb >= 0 && posb < CAPC) g_keyB[b][posb] = keyb;

        bool isf = fg_cand(roi, vb, vbits, pix, Bf, Tf);
        ull keyf = 0;
        if (isf) {
            float u = uf[pix];
            float s = logf(v) - logf(-logf(u));
            atomicAdd(&shf[sbucket(s)], 1u);
            keyf = (((ull)fmono(s)) << 32) | (u32)(HWN - 1 - pix);
        }
        int posf = warp_append(&g_nF[b], isf);
        if (posf >= 0 && posf < CAPC) g_keyF[b][posf] = keyf;
    }
    __syncthreads();
    for (int j = tid; j < NBINS; j += 1024) {
        u32 c = shf[j]; if (c) atomicAdd(&g_hist_sf[b][j], c);
        u32 d = shb[j]; if (d) atomicAdd(&g_hist_sb[b][j], d);
    }
}

// parallel score scans
__global__ void k_scanScores() {
    __shared__ int res[2];
    int b = blockIdx.x, which = blockIdx.y;  // 0 = fg, 1 = bg
    int K;
    const u32* hist;
    if (which == 0) {
        int nfg = g_nfg[b];
        K = g_deg[b] ? 0 : (nfg < 100 ? nfg : 100);
        hist = g_hist_sf[b];
    } else {
        K = g_deg[b] ? 0 : 100;
        hist = g_hist_sb[b];
    }
    find_bucket_256(hist, K, false, res);
    if (threadIdx.x == 0) {
        if (which == 0) { g_Bsf[b] = res[0]; g_needSf[b] = res[1]; }
        else            { g_Bsb[b] = res[0]; g_needSb[b] = res[1]; }
    }
}

__device__ __forceinline__ void mark_seed(ull* seedbase, int b, int pix) {
    int row = pix >> 9, col = pix & 511;
    atomicOr(&seedbase[(size_t)b * HN * 8 + (size_t)row * 8 + (col >> 6)],
             1ull << (col & 63));
}

// read compacted keys: mark sure seeds, collect score boundary keys
__global__ void k_markScores() {
    int b = blockIdx.x;
    int side = blockIdx.y;                 // 0 = fg, 1 = bg
    int cnt = side ? g_nB[b] : g_nF[b];
    if (cnt > CAPC) cnt = CAPC;
    int Bs  = side ? g_Bsb[b] : g_Bsf[b];
    const ull* keys = side ? g_keyB[b] : g_keyF[b];
    ull* seed = side ? &g_bgseed[0][0][0] : &g_fgseed[0][0][0];
    int* lcnt = side ? &g_cntSB[b] : &g_cntSF[b];
    ull* list = side ? g_listSB[b] : g_listSF[b];
    int tid = threadIdx.x;
    int iters = (cnt + 1023) >> 10;
    for (int it = 0; it < iters; it++) {
        int i = it * 1024 + tid;
        bool inb = i < cnt;
        ull k = inb ? keys[i] : 0ull;
        int sb = -1;
        if (inb) sb = sbucket(fmono_inv((u32)(k >> 32)));
        if (inb && sb > Bs) {
            int pix = HWN - 1 - (int)(k & 0xFFFFFFFFull);
            mark_seed(seed, b, pix);
        }
        int pos = warp_append(lcnt, inb && (sb == Bs));
        if (pos >= 0 && pos < CAP) list[pos] = k;
    }
}

__global__ void k_refineScores() {
    int b = blockIdx.x, which = blockIdx.y;  // 0 = fg, 1 = bg
    int cnt = which ? g_cntSB[b] : g_cntSF[b];
    if (cnt > CAP) cnt = CAP;
    int need = which ? g_needSb[b] : g_needSf[b];
    if (need <= 0) return;
    const ull* list = which ? g_listSB[b] : g_listSF[b];
    ull T = radix_kth_largest(list, cnt, need);
    ull* seed = which ? &g_bgseed[0][0][0] : &g_fgseed[0][0][0];
    for (int i = threadIdx.x; i < cnt; i += blockDim.x) {
        ull k = list[i];
        if (k >= T) {
            int pix = (int)((u32)(HWN - 1) - (u32)(k & 0xFFFFFFFFull));
            mark_seed(seed, b, pix);
        }
    }
}

// 3x3 dilation of both seed maps + compose float32 output
__global__ void k_output(float* __restrict__ out) {
    __shared__ ull sv[2][8];
    __shared__ ull sh2[2][8];
    int t = blockIdx.x;
    int b = t >> 9;
    int row = t & 511;
    int c = threadIdx.x;
    if (c < 16) {
        int q = c >> 3, w = c & 7;
        const ull* seed = q ? &g_bgseed[0][0][0] : &g_fgseed[0][0][0];
        size_t basei = (size_t)b * HN * 8;
        ull v = seed[basei + (size_t)row * 8 + w];
        if (row > 0)      v |= seed[basei + (size_t)(row - 1) * 8 + w];
        if (row < HN - 1) v |= seed[basei + (size_t)(row + 1) * 8 + w];
        sv[q][w] = v;
    }
    __syncthreads();
    if (c < 16) {
        int q = c >> 3, w = c & 7;
        ull m = sv[q][w];
        ull hh = m | (m << 1) | (m >> 1);
        if (w > 0) hh |= sv[q][w - 1] >> 63;
        if (w < 7) hh |= sv[q][w + 1] << 63;
        sh2[q][w] = hh;
    }
    __syncthreads();
    int w = c >> 6, bit = c & 63;
    int f = (int)((sh2[0][w] >> bit) & 1ull);
    int g = (int)((sh2[1][w] >> bit) & 1ull);
    float val;
    if (f && !g)      val = 1.0f;
    else if (g && !f) val = 0.0f;
    else              val = -255.0f;
    out[(size_t)b * HWN + (size_t)row * WN + c] = val;
}

// ------------------------------ launch ------------------------------
extern "C" void kernel_launch(void* const* d_in, const int* in_sizes, int n_in,
                              void* d_out, int out_size) {
    (void)out_size;
    const float* big[3] = {nullptr, nullptr, nullptr};
    const float* rt = nullptr;
    int nb = 0;
    for (int i = 0; i < n_in && i < 4; i++) {
        if (in_sizes[i] == BN) rt = (const float*)d_in[i];
        else if (nb < 3)       big[nb++] = (const float*)d_in[i];
    }
    const float* x   = big[0];
    const float* ufg = big[1];
    const float* ubg = big[2];
    float* out = (float*)d_out;

    k_zero<<<1024, 256>>>();
    k_prep<<<BN * 8, 1024>>>(x, rt);
    k_erode_h<<<(BN * HN + 255) / 256, 256>>>();
    k_erode_v<<<BN * HN * 8 / 256, 256>>>();
    k_scanBG<<<BN, 256>>>();
    k_roiHistCollectB<<<BN * 8, 1024>>>(x);
    k_scanFG<<<BN, 256>>>();
    k_collectF<<<BN * 8, 1024>>>(x);
    k_refine1<<<dim3(BN, 2), 256>>>();
    k_scoreCompact<<<BN * 8, 1024>>>(x, ufg, ubg);
    k_scanScores<<<dim3(BN, 2), 256>>>();
    k_markScores<<<dim3(BN, 2), 1024>>>();
    k_refineScores<<<dim3(BN, 2), 256>>>();
    k_output<<<BN * HN, 512>>>(out);
}

// round 10
// speedup vs baseline: 1.6663x; 1.1144x over previous
#include <cuda_runtime.h>
#include <cuda_bf16.h>
#include <math.h>

// ---------------------------------------------------------------------------
// TCAMSeeder exact port. R10: two-level (64-coarse + exact boundary radix)
// selection with NON-ATOMIC u8 shared counters, deferred stage-1 boundaries,
// 7 fused kernels, float4 streaming.
// side index convention: 0 = fg, 1 = bg.
// ---------------------------------------------------------------------------

#define BN    64
#define HN    512
#define WN    512
#define HWN   262144
#define NBGC  78643
#define CAPP  16384
#define CAPC  79872
#define CAPL  16384

typedef unsigned long long ull;
typedef unsigned int       u32;
typedef unsigned char      u8;

// ------------------------------ device scratch ------------------------------
__device__ ull g_pre[BN][HN * 8];     // pre-erosion bitmap
__device__ ull g_er [BN][HN * 8];     // eroded roi bitmap
__device__ u32 g_ch_all[BN][64];      // coarse value hist, all pixels
__device__ u32 g_ch_s[2][BN][64];     // coarse score hists
__device__ u32 g_minb[BN], g_maxb[BN];
__device__ int g_nfg[BN], g_deg[BN];
__device__ int g_BbC[BN], g_needB[BN];   // bg stage-1 coarse boundary
__device__ int g_BfC[BN], g_needF[BN];   // fg stage-1 coarse boundary
__device__ ull g_key[2][BN][CAPC];    // compacted candidate score keys
__device__ int g_n[2][BN];
__device__ ull g_p1[2][BN][CAPP];     // stage-1 boundary keys
__device__ ull g_ps[2][BN][CAPP];     // matching score keys
__device__ int g_np[2][BN];
__device__ ull g_listS[2][BN][CAPL];  // score boundary keys
__device__ int g_lc[2][BN];
__device__ ull g_seed[2][BN][HN * 8];

// ------------------------------ helpers ------------------------------
__device__ __forceinline__ int cbin(float v) {        // v > 0, monotone
    int k = (int)(v * 64.0f);
    return k > 63 ? 63 : k;
}
__device__ __forceinline__ int csbin(float s) {       // s in (-21, 16.3)
    int k = (int)((s + 24.0f) * 1.6f);
    if (k < 0) k = 0;
    if (k > 63) k = 63;
    return k;
}
__device__ __forceinline__ u32 fmono(float f) {
    u32 b = __float_as_uint(f);
    return (b & 0x80000000u) ? ~b : (b | 0x80000000u);
}
__device__ __forceinline__ float fmono_inv(u32 m) {
    u32 b = (m & 0x80000000u) ? (m ^ 0x80000000u) : ~m;
    return __uint_as_float(b);
}

// exact m-th largest 64-bit key among list[0..cnt) (block-collective)
__device__ __forceinline__ ull radix_kth_largest(const ull* __restrict__ list,
                                                 int cnt, int need) {
    __shared__ u32 rh[256];
    __shared__ ull s_pref;
    __shared__ int s_nd;
    int tid = threadIdx.x;
    if (tid == 0) { s_pref = 0ull; s_nd = need; }
    __syncthreads();
    for (int by = 7; by >= 0; --by) {
        for (int j = tid; j < 256; j += blockDim.x) rh[j] = 0;
        __syncthreads();
        ull mask = (by == 7) ? 0ull : (~0ull << (8 * (by + 1)));
        ull pref = s_pref;
        for (int i = tid; i < cnt; i += blockDim.x) {
            ull k = list[i];
            if (((k ^ pref) & mask) == 0ull)
                atomicAdd(&rh[(int)((k >> (8 * by)) & 255ull)], 1u);
        }
        __syncthreads();
        if (tid == 0) {
            int nd = s_nd; int cum = 0; int sel = 0;
            for (int v = 255; v >= 0; --v) {
                u32 c = rh[v];
                if (cum + (int)c >= nd) { sel = v; s_nd = nd - cum; break; }
                cum += c;
            }
            s_pref = pref | (((ull)sel) << (8 * by));
        }
        __syncthreads();
    }
    return s_pref;
}

// batched warp append: each lane contributes cnt (0..4) keys from loc[]
__device__ __forceinline__ void append_batch(ull* __restrict__ arr, int* ctr,
                                             const ull* loc, int cnt, int cap) {
    int lane = threadIdx.x & 31;
    int incl = cnt;
#pragma unroll
    for (int o = 1; o < 32; o <<= 1) {
        int t = __shfl_up_sync(0xFFFFFFFFu, incl, o);
        if (lane >= o) incl += t;
    }
    int tot = __shfl_sync(0xFFFFFFFFu, incl, 31);
    if (tot) {
        int base = 0;
        if (lane == 0) base = atomicAdd(ctr, tot);
        base = __shfl_sync(0xFFFFFFFFu, base, 0);
        int off = base + incl - cnt;
        for (int j = 0; j < cnt; j++) {
            int p = off + j;
            if (p < cap) arr[p] = loc[j];
        }
    }
}
// same but writes two parallel arrays
__device__ __forceinline__ void append_batch2(ull* __restrict__ a1, ull* __restrict__ a2,
                                              int* ctr, const ull* l1, const ull* l2,
                                              int cnt, int cap) {
    int lane = threadIdx.x & 31;
    int incl = cnt;
#pragma unroll
    for (int o = 1; o < 32; o <<= 1) {
        int t = __shfl_up_sync(0xFFFFFFFFu, incl, o);
        if (lane >= o) incl += t;
    }
    int tot = __shfl_sync(0xFFFFFFFFu, incl, 31);
    if (tot) {
        int base = 0;
        if (lane == 0) base = atomicAdd(ctr, tot);
        base = __shfl_sync(0xFFFFFFFFu, base, 0);
        int off = base + incl - cnt;
        for (int j = 0; j < cnt; j++) {
            int p = off + j;
            if (p < cap) { a1[p] = l1[j]; a2[p] = l2[j]; }
        }
    }
}
// single-pred warp append (rare events)
__device__ __forceinline__ int warp_append1(int* ctr, bool pred) {
    int lane = threadIdx.x & 31;
    u32 m = __ballot_sync(0xFFFFFFFFu, pred);
    int pos = -1;
    if (m) {
        int leader = __ffs(m) - 1;
        int base = 0;
        if (lane == leader) base = atomicAdd(ctr, __popc(m));
        base = __shfl_sync(0xFFFFFFFFu, base, leader);
        if (pred) pos = base + __popc(m & ((1u << lane) - 1u));
    }
    return pos;
}
__device__ __forceinline__ void mark_seed(ull* seedimg, int pix) {
    atomicOr(&seedimg[(pix >> 9) * 8 + ((pix & 511) >> 6)], 1ull << (pix & 63));
}

// ------------------------------ kernels ------------------------------

__global__ void k_zero() {
    int i = blockIdx.x * blockDim.x + threadIdx.x;
    int stride = gridDim.x * blockDim.x;
    ull* seeds = &g_seed[0][0][0];
    for (int j = i; j < 2 * BN * HN * 8; j += stride) seeds[j] = 0ull;
    u32* h1 = &g_ch_all[0][0];
    for (int j = i; j < BN * 64; j += stride) h1[j] = 0;
    u32* h2 = &g_ch_s[0][0][0];
    for (int j = i; j < 2 * BN * 64; j += stride) h2[j] = 0;
    if (i < BN) {
        g_n[0][i] = 0;  g_n[1][i] = 0;
        g_np[0][i] = 0; g_np[1][i] = 0;
        g_lc[0][i] = 0; g_lc[1][i] = 0;
        g_minb[i] = 0xFFFFFFFFu; g_maxb[i] = 0u;
    }
}

// P1: read x -> pre-erosion bitmap, minmax, coarse all-pixel value hist
__global__ void __launch_bounds__(256) k_prep(const float* __restrict__ x,
                                              const float* __restrict__ rt) {
    __shared__ u8 sc[256 * 68];
    int b = blockIdx.x >> 4;
    int chunk = blockIdx.x & 15;
    int tid = threadIdx.x;
    int lane = tid & 31;
    for (int j = tid; j < 256 * 68 / 4; j += 256) ((u32*)sc)[j] = 0;
    float th = rt[b];
    float thA = (th == 0.0f) ? 1.0f : ((th == 255.0f) ? 254.0f : th);
    u32 mn = 0xFFFFFFFFu, mx = 0u;
    const float4* xb4 = (const float4*)(x + (size_t)b * HWN);
    u32* bm = (u32*)g_pre[b];
    int base = chunk * 4096;
    __syncthreads();
    for (int it = 0; it < 16; it++) {
        int gf4 = base + it * 256 + tid;
        float4 xv = xb4[gf4];
        float e0 = xv.x, e1 = xv.y, e2 = xv.z, e3 = xv.w;
        u32 nib = 0;
        {
            float cam = e0; u32 cb = __float_as_uint(cam); mn = min(mn, cb); mx = max(mx, cb);
            sc[tid * 68 + cbin(cam + 1e-8f)]++;
            if (floorf(cam * 255.0f) > thA) nib |= 1u;
        }
        {
            float cam = e1; u32 cb = __float_as_uint(cam); mn = min(mn, cb); mx = max(mx, cb);
            sc[tid * 68 + cbin(cam + 1e-8f)]++;
            if (floorf(cam * 255.0f) > thA) nib |= 2u;
        }
        {
            float cam = e2; u32 cb = __float_as_uint(cam); mn = min(mn, cb); mx = max(mx, cb);
            sc[tid * 68 + cbin(cam + 1e-8f)]++;
            if (floorf(cam * 255.0f) > thA) nib |= 4u;
        }
        {
            float cam = e3; u32 cb = __float_as_uint(cam); mn = min(mn, cb); mx = max(mx, cb);
            sc[tid * 68 + cbin(cam + 1e-8f)]++;
            if (floorf(cam * 255.0f) > thA) nib |= 8u;
        }
        u32 vv = nib << (4 * (lane & 7));
        vv |= __shfl_xor_sync(0xFFFFFFFFu, vv, 1);
        vv |= __shfl_xor_sync(0xFFFFFFFFu, vv, 2);
        vv |= __shfl_xor_sync(0xFFFFFFFFu, vv, 4);
        if ((lane & 7) == 0) bm[gf4 >> 3] = vv;
    }
    __syncthreads();
    if (tid < 64) {
        u32 s = 0;
        for (int t2 = 0; t2 < 256; t2++) s += sc[t2 * 68 + tid];
        if (s) atomicAdd(&g_ch_all[b][tid], s);
    }
    // minmax reduce
    for (int o = 16; o; o >>= 1) {
        mn = min(mn, __shfl_down_sync(0xFFFFFFFFu, mn, o));
        mx = max(mx, __shfl_down_sync(0xFFFFFFFFu, mx, o));
    }
    __shared__ u32 smn[8], smx[8];
    if (lane == 0) { smn[tid >> 5] = mn; smx[tid >> 5] = mx; }
    __syncthreads();
    if (tid == 0) {
        for (int w = 1; w < 8; w++) { mn = min(mn, smn[w]); mx = max(mx, smx[w]); }
        atomicMin(&g_minb[b], mn);
        atomicMax(&g_maxb[b], mx);
    }
}

// Fused: erosion (h+v) + roi popcount + bg coarse scan + roi coarse hist + fg scan
__global__ void __launch_bounds__(1024) k_erode(const float* __restrict__ x) {
    extern __shared__ char dsm[];
    ull* s_pre = (ull*)dsm;                       // 4096 ull
    ull* s_hb  = (ull*)(dsm + 32768);             // 4096 ull
    u8*  sc    = (u8*)(dsm + 65536);              // 1024*68
    u32* bh    = (u32*)(dsm + 65536 + 69632);     // 64
    int* red   = (int*)(dsm + 65536 + 69632 + 256);  // 32
    int* sres  = (int*)(dsm + 65536 + 69632 + 256 + 128); // 4
    int b = blockIdx.x;
    int tid = threadIdx.x;
    int lane = tid & 31;

    // load pre bitmap
    for (int i = tid; i < 4096; i += 1024) s_pre[i] = g_pre[b][i];
    __syncthreads();
    // horizontal erode
    for (int i = tid; i < 4096; i += 1024) {
        int row8 = i & ~7, w = i & 7;
        ull av = s_pre[i];
        ull lo = w ? s_pre[i - 1] : ~0ull;
        ull hi = (w < 7) ? s_pre[i + 1] : ~0ull;
        ull r = av;
#pragma unroll
        for (int d = 1; d <= 5; d++)
            r &= ((av >> d) | (hi << (64 - d))) & ((av << d) | (lo >> (64 - d)));
        s_hb[i] = r;
        (void)row8;
    }
    __syncthreads();
    // vertical erode + popcount, store roi back into s_pre
    int pc = 0;
    for (int i = tid; i < 4096; i += 1024) {
        int row = i >> 3, w = i & 7;
        ull r = ~0ull;
#pragma unroll
        for (int d = -5; d <= 5; d++) {
            int rr = row + d;
            if (rr >= 0 && rr < HN) r &= s_hb[rr * 8 + w];
        }
        g_er[b][i] = r;
        s_pre[i] = r;
        pc += __popcll(r);
    }
    for (int o = 16; o; o >>= 1) pc += __shfl_down_sync(0xFFFFFFFFu, pc, o);
    if (lane == 0) red[tid >> 5] = pc;
    if (tid < 64) bh[tid] = g_ch_all[b][tid];
    __syncthreads();
    if (tid == 0) {
        int cnt = 0;
        for (int w = 0; w < 32; w++) cnt += red[w];
        int nfg = (int)floorf(0.3f * (float)cnt);
        g_nfg[b] = nfg;
        g_deg[b] = (g_minb[b] == g_maxb[b]) ? 1 : 0;
        // bg coarse crossing (ascending)
        int cum = 0, Bb = 64, nd = 0;
        for (int j = 0; j < 64; j++) {
            int c = (int)bh[j];
            if (cum + c >= NBGC) { Bb = j; nd = NBGC - cum; break; }
            cum += c;
        }
        g_BbC[b] = Bb; g_needB[b] = nd;
        sres[0] = nfg;
    }
    // phase B: roi coarse hist from x
    for (int j = tid * 17; j < tid * 17 + 17; j++) ((u32*)sc)[j] = 0;
    __syncthreads();
    const float4* xb4 = (const float4*)(x + (size_t)b * HWN);
    for (int it = 0; it < 64; it++) {
        int gf4 = it * 1024 + tid;
        int p = gf4 * 4;
        ull wbits = s_pre[(p >> 9) * 8 + ((p & 511) >> 6)];
        u32 bits4 = (u32)(wbits >> (p & 63)) & 0xFu;
        if (bits4) {
            float4 xv = xb4[gf4];
            if (bits4 & 1u) sc[tid * 68 + cbin(xv.x + 1e-8f)]++;
            if (bits4 & 2u) sc[tid * 68 + cbin(xv.y + 1e-8f)]++;
            if (bits4 & 4u) sc[tid * 68 + cbin(xv.z + 1e-8f)]++;
            if (bits4 & 8u) sc[tid * 68 + cbin(xv.w + 1e-8f)]++;
        }
    }
    __syncthreads();
    if (tid < 64) {
        u32 s = 0;
        for (int t2 = 0; t2 < 1024; t2++) s += sc[t2 * 68 + tid];
        bh[tid] = s;
    }
    __syncthreads();
    if (tid == 0) {
        int nfg = sres[0];
        int Bf = 64, nd = 0;
        if (nfg > 0) {
            int cum = 0;
            for (int j = 63; j >= 0; j--) {
                int c = (int)bh[j];
                if (cum + c >= nfg) { Bf = j; nd = nfg - cum; break; }
                cum += c;
            }
        }
        g_BfC[b] = Bf; g_needF[b] = nd;
    }
}

// P3: score pass — compact sure-candidate score keys + coarse score hists +
// stage-1 boundary pairs (deferred refinement)
__global__ void __launch_bounds__(256) k_score(const float* __restrict__ x,
                                               const float* __restrict__ ufg,
                                               const float* __restrict__ ubg) {
    __shared__ u8 scf[256 * 68];
    __shared__ u8 scb[256 * 68];
    int b = blockIdx.x >> 4;
    int chunk = blockIdx.x & 15;
    int tid = threadIdx.x;
    for (int j = tid; j < 256 * 68 / 4; j += 256) {
        ((u32*)scf)[j] = 0; ((u32*)scb)[j] = 0;
    }
    int BbC = g_BbC[b], BfC = g_BfC[b];
    const float4* xb4 = (const float4*)(x + (size_t)b * HWN);
    const float4* uf4 = (const float4*)(ufg + (size_t)b * HWN);
    const float4* ub4 = (const float4*)(ubg + (size_t)b * HWN);
    const u32* erw = (const u32*)g_er[b];
    int base = chunk * 4096;
    __syncthreads();
    for (int it = 0; it < 16; it++) {
        int gf4 = base + it * 256 + tid;
        int p0 = gf4 * 4;
        float4 xv = xb4[gf4];
        float4 uf = uf4[gf4];
        float4 ub = ub4[gf4];
        u32 rbits = (erw[gf4 >> 3] >> ((gf4 & 7) * 4)) & 0xFu;
        float ex[4] = {xv.x, xv.y, xv.z, xv.w};
        float eu[4] = {uf.x, uf.y, uf.z, uf.w};
        float eb[4] = {ub.x, ub.y, ub.z, ub.w};
        ull sureF[4], sureB[4];
        int nSf = 0, nSb = 0;
#pragma unroll
        for (int k = 0; k < 4; k++) {
            int pix = p0 + k;
            float v = ex[k] + 1e-8f;
            int c = cbin(v);
            int roi = (rbits >> k) & 1;
            // bg
            bool bs = c < BbC, bb = (c == BbC);
            ull skb = 0, kb1 = 0;
            if (bs | bb) {
                float s = logf(fmaxf(1.0f - v, 0.0f) + 1e-8f) - logf(-logf(eb[k]));
                skb = (((ull)fmono(s)) << 32) | (u32)(HWN - 1 - pix);
                if (bs) { scb[tid * 68 + csbin(s)]++; sureB[nSb++] = skb; }
                else kb1 = ~((((ull)__float_as_uint(v)) << 32) | (u32)pix);
            }
            int posb = warp_append1(&g_np[1][b], bb);
            if (posb >= 0 && posb < CAPP) { g_p1[1][b][posb] = kb1; g_ps[1][b][posb] = skb; }
            // fg
            bool fs = roi && (c > BfC), fb = roi && (c == BfC);
            ull skf = 0, kf1 = 0;
            if (fs | fb) {
                float s = logf(v) - logf(-logf(eu[k]));
                skf = (((ull)fmono(s)) << 32) | (u32)(HWN - 1 - pix);
                if (fs) { scf[tid * 68 + csbin(s)]++; sureF[nSf++] = skf; }
                else kf1 = (((ull)__float_as_uint(v)) << 32) | (u32)(HWN - 1 - pix);
            }
            int posf = warp_append1(&g_np[0][b], fb);
            if (posf >= 0 && posf < CAPP) { g_p1[0][b][posf] = kf1; g_ps[0][b][posf] = skf; }
        }
        append_batch(g_key[0][b], &g_n[0][b], sureF, nSf, CAPC);
        append_batch(g_key[1][b], &g_n[1][b], sureB, nSb, CAPC);
    }
    __syncthreads();
    if (tid < 64) {
        u32 sf = 0, sb = 0;
        for (int t2 = 0; t2 < 256; t2++) { sf += scf[t2 * 68 + tid]; sb += scb[t2 * 68 + tid]; }
        if (sf) atomicAdd(&g_ch_s[0][b][tid], sf);
        if (sb) atomicAdd(&g_ch_s[1][b][tid], sb);
    }
}

// stage-1 boundary refinement: pick exact winners, append their score keys
__global__ void __launch_bounds__(256) k_refine1() {
    int b = blockIdx.x, side = blockIdx.y;   // 0=fg, 1=bg
    int need = side ? g_needB[b] : g_needF[b];
    int cnt = g_np[side][b]; if (cnt > CAPP) cnt = CAPP;
    if (need <= 0) return;
    ull T = radix_kth_largest(g_p1[side][b], cnt, need);
    for (int i = threadIdx.x; i < cnt; i += 256) {
        if (g_p1[side][b][i] >= T) {
            ull sk = g_ps[side][b][i];
            int pos = atomicAdd(&g_n[side][b], 1);
            if (pos < CAPC) g_key[side][b][pos] = sk;
            float s = fmono_inv((u32)(sk >> 32));
            atomicAdd(&g_ch_s[side][b][csbin(s)], 1u);
        }
    }
}

// fused: coarse score scan + sure marks + boundary collect + exact refine + mark
__global__ void __launch_bounds__(1024) k_mark() {
    __shared__ u32 hh[64];
    __shared__ int sres[2];
    int b = blockIdx.x, side = blockIdx.y;   // 0=fg, 1=bg
    int tid = threadIdx.x;
    int K;
    if (side == 0) {
        int nf = g_nfg[b];
        K = g_deg[b] ? 0 : (nf < 100 ? nf : 100);
    } else {
        K = g_deg[b] ? 0 : 100;
    }
    if (tid < 64) hh[tid] = g_ch_s[side][b][tid];
    __syncthreads();
    if (tid == 0) {
        int Bs = 64, need = 0;
        if (K > 0) {
            int cum = 0;
            for (int j = 63; j >= 0; j--) {
                int c = (int)hh[j];
                if (cum + c >= K) { Bs = j; need = K - cum; break; }
                cum += c;
            }
        }
        sres[0] = Bs; sres[1] = need;
    }
    __syncthreads();
    int Bs = sres[0], need = sres[1];
    int n = g_n[side][b]; if (n > CAPC) n = CAPC;
    const ull* keys = g_key[side][b];
    ull* seed = g_seed[side][b];
    int iters = (n + 1023) >> 10;
    for (int it = 0; it < iters; it++) {
        int i = it * 1024 + tid;
        bool inb = i < n;
        ull k = inb ? keys[i] : 0ull;
        int cb = -1;
        if (inb) cb = csbin(fmono_inv((u32)(k >> 32)));
        if (inb && cb > Bs) mark_seed(seed, HWN - 1 - (int)(k & 0xFFFFFFFFull));
        int pos = warp_append1(&g_lc[side][b], inb && (cb == Bs));
        if (pos >= 0 && pos < CAPL) g_listS[side][b][pos] = k;
    }
    __threadfence();
    __syncthreads();
    if (need > 0) {
        int cnt2 = g_lc[side][b]; if (cnt2 > CAPL) cnt2 = CAPL;
        ull T = radix_kth_largest(g_listS[side][b], cnt2, need);
        for (int i = tid; i < cnt2; i += 1024) {
            ull k = g_listS[side][b][i];
            if (k >= T) mark_seed(seed, HWN - 1 - (int)(k & 0xFFFFFFFFull));
        }
    }
}

// 3x3 dilation + compose float32 output
__global__ void k_output(float* __restrict__ out) {
    __shared__ ull sv[2][8];
    __shared__ ull sh2[2][8];
    int t = blockIdx.x;
    int b = t >> 9;
    int row = t & 511;
    int c = threadIdx.x;
    if (c < 16) {
        int q = c >> 3, w = c & 7;
        const ull* seed = g_seed[q][b];
        ull v = seed[row * 8 + w];
        if (row > 0)      v |= seed[(row - 1) * 8 + w];
        if (row < HN - 1) v |= seed[(row + 1) * 8 + w];
        sv[q][w] = v;
    }
    __syncthreads();
    if (c < 16) {
        int q = c >> 3, w = c & 7;
        ull m = sv[q][w];
        ull hh = m | (m << 1) | (m >> 1);
        if (w > 0) hh |= sv[q][w - 1] >> 63;
        if (w < 7) hh |= sv[q][w + 1] << 63;
        sh2[q][w] = hh;
    }
    __syncthreads();
    int w = c >> 6, bit = c & 63;
    int f = (int)((sh2[0][w] >> bit) & 1ull);
    int g = (int)((sh2[1][w] >> bit) & 1ull);
    float val;
    if (f && !g)      val = 1.0f;
    else if (g && !f) val = 0.0f;
    else              val = -255.0f;
    out[(size_t)b * HWN + (size_t)row * WN + c] = val;
}

// ------------------------------ launch ------------------------------
extern "C" void kernel_launch(void* const* d_in, const int* in_sizes, int n_in,
                              void* d_out, int out_size) {
    (void)out_size;
    const float* big[3] = {nullptr, nullptr, nullptr};
    const float* rt = nullptr;
    int nb = 0;
    for (int i = 0; i < n_in && i < 4; i++) {
        if (in_sizes[i] == BN) rt = (const float*)d_in[i];
        else if (nb < 3)       big[nb++] = (const float*)d_in[i];
    }
    const float* x   = big[0];
    const float* ufg = big[1];
    const float* ubg = big[2];
    float* out = (float*)d_out;

    const int ERODE_SMEM = 65536 + 69632 + 256 + 128 + 64;
    cudaFuncSetAttribute(k_erode, cudaFuncAttributeMaxDynamicSharedMemorySize, ERODE_SMEM);

    k_zero<<<512, 256>>>();
    k_prep<<<BN * 16, 256>>>(x, rt);
    k_erode<<<BN, 1024, ERODE_SMEM>>>(x);
    k_score<<<BN * 16, 256>>>(x, ufg, ubg);
    k_refine1<<<dim3(BN, 2), 256>>>();
    k_mark<<<dim3(BN, 2), 1024>>>();
    k_output<<<BN * HN, 512>>>(out);
}

// round 11
// speedup vs baseline: 1.7703x; 1.0624x over previous
#include <cuda_runtime.h>
#include <cuda_bf16.h>
#include <math.h>

// ---------------------------------------------------------------------------
// TCAMSeeder exact port. R11: no logf in the streaming pass — candidates are
// recorded as (fmono(u), pix); top-k by Gumbel score computed sparsely using
// the provable bound s = log(p)+g(u) <= g(u) with runtime-verified u-tiers.
// side convention: 0 = fg, 1 = bg.
// ---------------------------------------------------------------------------

#define BN    64
#define HN    512
#define WN    512
#define HWN   262144
#define NBGC  78643
#define CAPP  16384
#define CAPC  79872

#define UCUT0 0xBF7C0000u   // fmono(0.984375f)  (63/64)
#define UCUT1 0xBF400000u   // fmono(0.75f)

typedef unsigned long long ull;
typedef unsigned int       u32;
typedef unsigned char      u8;

// ------------------------------ device scratch ------------------------------
__device__ ull g_pre[BN][HN * 8];
__device__ ull g_er [BN][HN * 8];
__device__ u32 g_ch_all[BN][64];
__device__ u32 g_ch_roi[BN][64];
__device__ u32 g_minb[BN], g_maxb[BN];
__device__ int g_nfg[BN], g_deg[BN];
__device__ int g_BbC[BN], g_needB[BN];
__device__ int g_BfC[BN], g_needF[BN];
__device__ int g_done1[BN], g_done2[BN];
__device__ ull g_rec[2][BN][CAPC];    // candidate records (fmono(u)<<32)|pix
__device__ int g_n[2][BN];
__device__ ull g_p1[2][BN][CAPP];     // stage-1 boundary value keys
__device__ ull g_pr[2][BN][CAPP];     // matching records
__device__ int g_np[2][BN];
__device__ ull g_sk[2][BN][CAPC];     // score keys scratch (top-k kernel)
__device__ ull g_seed[2][BN][HN * 8];

// ------------------------------ helpers ------------------------------
__device__ __forceinline__ int cbin(float v) {
    int k = (int)(v * 64.0f);
    return k > 63 ? 63 : k;
}
__device__ __forceinline__ u32 fmono(float f) {
    u32 b = __float_as_uint(f);
    return (b & 0x80000000u) ? ~b : (b | 0x80000000u);
}
__device__ __forceinline__ float fmono_inv(u32 m) {
    u32 b = (m & 0x80000000u) ? (m ^ 0x80000000u) : ~m;
    return __uint_as_float(b);
}
__device__ __forceinline__ void mark_seed(ull* seedimg, int pix) {
    atomicOr(&seedimg[(pix >> 9) * 8 + ((pix & 511) >> 6)], 1ull << (pix & 63));
}

// exact m-th largest 64-bit key among list[0..cnt) (block-collective)
__device__ __forceinline__ ull radix_kth_largest(const ull* __restrict__ list,
                                                 int cnt, int need) {
    __shared__ u32 rh[256];
    __shared__ ull s_pref;
    __shared__ int s_nd;
    int tid = threadIdx.x;
    if (tid == 0) { s_pref = 0ull; s_nd = need; }
    __syncthreads();
    for (int by = 7; by >= 0; --by) {
        for (int j = tid; j < 256; j += blockDim.x) rh[j] = 0;
        __syncthreads();
        ull mask = (by == 7) ? 0ull : (~0ull << (8 * (by + 1)));
        ull pref = s_pref;
        for (int i = tid; i < cnt; i += blockDim.x) {
            ull k = list[i];
            if (((k ^ pref) & mask) == 0ull)
                atomicAdd(&rh[(int)((k >> (8 * by)) & 255ull)], 1u);
        }
        __syncthreads();
        if (tid == 0) {
            int nd = s_nd; int cum = 0; int sel = 0;
            for (int v = 255; v >= 0; --v) {
                u32 c = rh[v];
                if (cum + (int)c >= nd) { sel = v; s_nd = nd - cum; break; }
                cum += c;
            }
            s_pref = pref | (((ull)sel) << (8 * by));
        }
        __syncthreads();
    }
    return s_pref;
}

// ------------------------------ kernels ------------------------------

__global__ void k_zero() {
    int i = blockIdx.x * blockDim.x + threadIdx.x;
    int stride = gridDim.x * blockDim.x;
    ull* seeds = &g_seed[0][0][0];
    for (int j = i; j < 2 * BN * HN * 8; j += stride) seeds[j] = 0ull;
    u32* h1 = &g_ch_all[0][0];
    u32* h2 = &g_ch_roi[0][0];
    for (int j = i; j < BN * 64; j += stride) { h1[j] = 0; h2[j] = 0; }
    if (i < BN) {
        g_n[0][i] = 0;  g_n[1][i] = 0;
        g_np[0][i] = 0; g_np[1][i] = 0;
        g_done1[i] = 0; g_done2[i] = 0;
        g_minb[i] = 0xFFFFFFFFu; g_maxb[i] = 0u;
    }
}

// P1: x -> pre-erosion bitmap, minmax, all-pixel 64-bin value hist; last block
// per image computes deg + bg coarse boundary.
__global__ void __launch_bounds__(256) k_prep(const float* __restrict__ x,
                                              const float* __restrict__ rt) {
    __shared__ u8 sc[256 * 68];
    __shared__ u32 smn[8], smx[8];
    int b = blockIdx.x >> 4;
    int chunk = blockIdx.x & 15;
    int tid = threadIdx.x, lane = tid & 31;
    for (int j = tid; j < 256 * 68 / 4; j += 256) ((u32*)sc)[j] = 0;
    float th = rt[b];
    float thA = (th == 0.0f) ? 1.0f : ((th == 255.0f) ? 254.0f : th);
    u32 mn = 0xFFFFFFFFu, mx = 0u;
    const float4* xb4 = (const float4*)(x + (size_t)b * HWN);
    u32* bm = (u32*)g_pre[b];
    int base = chunk * 4096;
    __syncthreads();
    for (int it = 0; it < 16; it++) {
        int gf4 = base + it * 256 + tid;
        float4 xv = xb4[gf4];
        float e[4] = {xv.x, xv.y, xv.z, xv.w};
        u32 nib = 0;
#pragma unroll
        for (int k = 0; k < 4; k++) {
            float cam = e[k];
            u32 cb2 = __float_as_uint(cam);
            mn = min(mn, cb2); mx = max(mx, cb2);
            sc[tid * 68 + cbin(cam + 1e-8f)]++;
            if (floorf(cam * 255.0f) > thA) nib |= (1u << k);
        }
        u32 vv = nib << (4 * (lane & 7));
        vv |= __shfl_xor_sync(0xFFFFFFFFu, vv, 1);
        vv |= __shfl_xor_sync(0xFFFFFFFFu, vv, 2);
        vv |= __shfl_xor_sync(0xFFFFFFFFu, vv, 4);
        if ((lane & 7) == 0) bm[gf4 >> 3] = vv;
    }
    __syncthreads();
    if (tid < 64) {
        u32 s = 0;
        for (int t2 = 0; t2 < 256; t2++) s += sc[t2 * 68 + tid];
        if (s) atomicAdd(&g_ch_all[b][tid], s);
    }
    for (int o = 16; o; o >>= 1) {
        mn = min(mn, __shfl_down_sync(0xFFFFFFFFu, mn, o));
        mx = max(mx, __shfl_down_sync(0xFFFFFFFFu, mx, o));
    }
    if (lane == 0) { smn[tid >> 5] = mn; smx[tid >> 5] = mx; }
    __syncthreads();
    if (tid == 0) {
        for (int w = 1; w < 8; w++) { mn = min(mn, smn[w]); mx = max(mx, smx[w]); }
        atomicMin(&g_minb[b], mn);
        atomicMax(&g_maxb[b], mx);
        __threadfence();
        int d = atomicAdd(&g_done1[b], 1);
        if (d == 15) {
            u32 mnv = atomicMin(&g_minb[b], 0xFFFFFFFFu);
            u32 mxv = atomicMax(&g_maxb[b], 0u);
            g_deg[b] = (mnv == mxv) ? 1 : 0;
            int cum = 0, Bb = 64, nd = 0;
            for (int j = 0; j < 64; j++) {
                int c = (int)atomicAdd(&g_ch_all[b][j], 0u);
                if (cum + c >= NBGC) { Bb = j; nd = NBGC - cum; break; }
                cum += c;
            }
            g_BbC[b] = Bb; g_needB[b] = nd;
        }
    }
}

// P2: 11x11 erosion (bit-packed, OOB=1) + roi popcount -> n_fg
__global__ void __launch_bounds__(1024) k_erode() {
    extern __shared__ ull dsm[];
    ull* s_pre = dsm;          // 4096
    ull* s_hb  = dsm + 4096;   // 4096
    __shared__ int red[32];
    int b = blockIdx.x, tid = threadIdx.x, lane = tid & 31;
    for (int i = tid; i < 4096; i += 1024) s_pre[i] = g_pre[b][i];
    __syncthreads();
    for (int i = tid; i < 4096; i += 1024) {
        int w = i & 7;
        ull av = s_pre[i];
        ull lo = w ? s_pre[i - 1] : ~0ull;
        ull hi = (w < 7) ? s_pre[i + 1] : ~0ull;
        ull r = av;
#pragma unroll
        for (int d = 1; d <= 5; d++)
            r &= ((av >> d) | (hi << (64 - d))) & ((av << d) | (lo >> (64 - d)));
        s_hb[i] = r;
    }
    __syncthreads();
    int pc = 0;
    for (int i = tid; i < 4096; i += 1024) {
        int row = i >> 3, w = i & 7;
        ull r = ~0ull;
#pragma unroll
        for (int d = -5; d <= 5; d++) {
            int rr = row + d;
            if (rr >= 0 && rr < HN) r &= s_hb[rr * 8 + w];
        }
        g_er[b][i] = r;
        pc += __popcll(r);
    }
    for (int o = 16; o; o >>= 1) pc += __shfl_down_sync(0xFFFFFFFFu, pc, o);
    if (lane == 0) red[tid >> 5] = pc;
    __syncthreads();
    if (tid == 0) {
        int c = 0;
        for (int w = 0; w < 32; w++) c += red[w];
        g_nfg[b] = (int)floorf(0.3f * (float)c);
    }
}

// P3: roi 64-bin value hist (skipped when n_fg==0); last block: fg boundary
__global__ void __launch_bounds__(256) k_roihist(const float* __restrict__ x) {
    __shared__ u8 sc[256 * 68];
    int b = blockIdx.x >> 4;
    int chunk = blockIdx.x & 15;
    int tid = threadIdx.x;
    int nfg = g_nfg[b];
    if (nfg > 0) {
        for (int j = tid; j < 256 * 68 / 4; j += 256) ((u32*)sc)[j] = 0;
        __syncthreads();
        const float4* xb4 = (const float4*)(x + (size_t)b * HWN);
        const u32* erw = (const u32*)g_er[b];
        int base = chunk * 4096;
        for (int it = 0; it < 16; it++) {
            int gf4 = base + it * 256 + tid;
            u32 rbits = (erw[gf4 >> 3] >> ((gf4 & 7) * 4)) & 0xFu;
            if (rbits) {
                float4 xv = xb4[gf4];
                if (rbits & 1u) sc[tid * 68 + cbin(xv.x + 1e-8f)]++;
                if (rbits & 2u) sc[tid * 68 + cbin(xv.y + 1e-8f)]++;
                if (rbits & 4u) sc[tid * 68 + cbin(xv.z + 1e-8f)]++;
                if (rbits & 8u) sc[tid * 68 + cbin(xv.w + 1e-8f)]++;
            }
        }
        __syncthreads();
        if (tid < 64) {
            u32 s = 0;
            for (int t2 = 0; t2 < 256; t2++) s += sc[t2 * 68 + tid];
            if (s) atomicAdd(&g_ch_roi[b][tid], s);
        }
        __syncthreads();
    }
    if (tid == 0) {
        __threadfence();
        int d = atomicAdd(&g_done2[b], 1);
        if (d == 15) {
            int n = g_nfg[b];
            int Bf = 64, nd = 0;
            if (n > 0) {
                int cum = 0;
                for (int j = 63; j >= 0; j--) {
                    int c = (int)atomicAdd(&g_ch_roi[b][j], 0u);
                    if (cum + c >= n) { Bf = j; nd = n - cum; break; }
                    cum += c;
                }
            }
            g_BfC[b] = Bf; g_needF[b] = nd;
        }
    }
}

// P4: streaming classify — emit candidate records + stage-1 boundary pairs.
// NO logf, NO shared memory, NO shfl-scan chains.
__global__ void __launch_bounds__(256) k_score(const float* __restrict__ x,
                                               const float* __restrict__ ufg,
                                               const float* __restrict__ ubg) {
    int b = blockIdx.x >> 4;
    int chunk = blockIdx.x & 15;
    int tid = threadIdx.x, lane = tid & 31;
    int BbC = g_BbC[b], BfC = g_BfC[b];
    const float4* xb4 = (const float4*)(x + (size_t)b * HWN);
    const float* ufp = ufg + (size_t)b * HWN;
    const float* ubp = ubg + (size_t)b * HWN;
    const u32* erw = (const u32*)g_er[b];
    int base = chunk * 4096;
    u32 lt = (1u << lane) - 1u;
    for (int it = 0; it < 16; it++) {
        int gf4 = base + it * 256 + tid;
        float4 xv = xb4[gf4];
        u32 rbits = (erw[gf4 >> 3] >> ((gf4 & 7) * 4)) & 0xFu;
        float vx[4] = {xv.x + 1e-8f, xv.y + 1e-8f, xv.z + 1e-8f, xv.w + 1e-8f};
        bool bs[4], bb[4], fs[4], fb[4];
        ull recB[4], recF[4], keyB[4], keyF[4];
#pragma unroll
        for (int k = 0; k < 4; k++) {
            float v = vx[k];
            int c = cbin(v);
            int pix = gf4 * 4 + k;
            int roi = (rbits >> k) & 1;
            bs[k] = c < BbC;  bb[k] = (c == BbC);
            fs[k] = roi && (c > BfC);  fb[k] = roi && (c == BfC);
            float uB = 0.0f, uF = 0.0f;
            if (bs[k] | bb[k]) uB = ubp[pix];
            if (fs[k] | fb[k]) uF = ufp[pix];
            recB[k] = (((ull)(__float_as_uint(uB) | 0x80000000u)) << 32) | (u32)pix;
            recF[k] = (((ull)(__float_as_uint(uF) | 0x80000000u)) << 32) | (u32)pix;
            u32 vb = __float_as_uint(v);
            keyB[k] = ~((((ull)vb) << 32) | (u32)pix);
            keyF[k] = (((ull)vb) << 32) | (u32)(HWN - 1 - pix);
        }
        // sure bg records
        {
            u32 m0 = __ballot_sync(~0u, bs[0]), m1 = __ballot_sync(~0u, bs[1]);
            u32 m2 = __ballot_sync(~0u, bs[2]), m3 = __ballot_sync(~0u, bs[3]);
            int p0 = __popc(m0), p01 = p0 + __popc(m1), p012 = p01 + __popc(m2);
            int tot = p012 + __popc(m3);
            int bse = 0;
            if (lane == 0 && tot) bse = atomicAdd(&g_n[1][b], tot);
            bse = __shfl_sync(~0u, bse, 0);
            if (bs[0]) { int j = bse + __popc(m0 & lt);        if (j < CAPC) g_rec[1][b][j] = recB[0]; }
            if (bs[1]) { int j = bse + p0 + __popc(m1 & lt);   if (j < CAPC) g_rec[1][b][j] = recB[1]; }
            if (bs[2]) { int j = bse + p01 + __popc(m2 & lt);  if (j < CAPC) g_rec[1][b][j] = recB[2]; }
            if (bs[3]) { int j = bse + p012 + __popc(m3 & lt); if (j < CAPC) g_rec[1][b][j] = recB[3]; }
        }
        // sure fg records
        {
            u32 m0 = __ballot_sync(~0u, fs[0]), m1 = __ballot_sync(~0u, fs[1]);
            u32 m2 = __ballot_sync(~0u, fs[2]), m3 = __ballot_sync(~0u, fs[3]);
            int p0 = __popc(m0), p01 = p0 + __popc(m1), p012 = p01 + __popc(m2);
            int tot = p012 + __popc(m3);
            int bse = 0;
            if (lane == 0 && tot) bse = atomicAdd(&g_n[0][b], tot);
            bse = __shfl_sync(~0u, bse, 0);
            if (fs[0]) { int j = bse + __popc(m0 & lt);        if (j < CAPC) g_rec[0][b][j] = recF[0]; }
            if (fs[1]) { int j = bse + p0 + __popc(m1 & lt);   if (j < CAPC) g_rec[0][b][j] = recF[1]; }
            if (fs[2]) { int j = bse + p01 + __popc(m2 & lt);  if (j < CAPC) g_rec[0][b][j] = recF[2]; }
            if (fs[3]) { int j = bse + p012 + __popc(m3 & lt); if (j < CAPC) g_rec[0][b][j] = recF[3]; }
        }
        // bg boundary pairs
        {
            u32 m0 = __ballot_sync(~0u, bb[0]), m1 = __ballot_sync(~0u, bb[1]);
            u32 m2 = __ballot_sync(~0u, bb[2]), m3 = __ballot_sync(~0u, bb[3]);
            int p0 = __popc(m0), p01 = p0 + __popc(m1), p012 = p01 + __popc(m2);
            int tot = p012 + __popc(m3);
            int bse = 0;
            if (lane == 0 && tot) bse = atomicAdd(&g_np[1][b], tot);
            bse = __shfl_sync(~0u, bse, 0);
            if (bb[0]) { int j = bse + __popc(m0 & lt);        if (j < CAPP) { g_p1[1][b][j] = keyB[0]; g_pr[1][b][j] = recB[0]; } }
            if (bb[1]) { int j = bse + p0 + __popc(m1 & lt);   if (j < CAPP) { g_p1[1][b][j] = keyB[1]; g_pr[1][b][j] = recB[1]; } }
            if (bb[2]) { int j = bse + p01 + __popc(m2 & lt);  if (j < CAPP) { g_p1[1][b][j] = keyB[2]; g_pr[1][b][j] = recB[2]; } }
            if (bb[3]) { int j = bse + p012 + __popc(m3 & lt); if (j < CAPP) { g_p1[1][b][j] = keyB[3]; g_pr[1][b][j] = recB[3]; } }
        }
        // fg boundary pairs
        {
            u32 m0 = __ballot_sync(~0u, fb[0]), m1 = __ballot_sync(~0u, fb[1]);
            u32 m2 = __ballot_sync(~0u, fb[2]), m3 = __ballot_sync(~0u, fb[3]);
            int p0 = __popc(m0), p01 = p0 + __popc(m1), p012 = p01 + __popc(m2);
            int tot = p012 + __popc(m3);
            int bse = 0;
            if (lane == 0 && tot) bse = atomicAdd(&g_np[0][b], tot);
            bse = __shfl_sync(~0u, bse, 0);
            if (fb[0]) { int j = bse + __popc(m0 & lt);        if (j < CAPP) { g_p1[0][b][j] = keyF[0]; g_pr[0][b][j] = recF[0]; } }
            if (fb[1]) { int j = bse + p0 + __popc(m1 & lt);   if (j < CAPP) { g_p1[0][b][j] = keyF[1]; g_pr[0][b][j] = recF[1]; } }
            if (fb[2]) { int j = bse + p01 + __popc(m2 & lt);  if (j < CAPP) { g_p1[0][b][j] = keyF[2]; g_pr[0][b][j] = recF[2]; } }
            if (fb[3]) { int j = bse + p012 + __popc(m3 & lt); if (j < CAPP) { g_p1[0][b][j] = keyF[3]; g_pr[0][b][j] = recF[3]; } }
        }
    }
}

// P5: stage-1 boundary refinement — append exact winners' records
__global__ void __launch_bounds__(256) k_refine1() {
    int b = blockIdx.x, side = blockIdx.y;
    int need = side ? g_needB[b] : g_needF[b];
    if (need <= 0) return;
    int cnt = g_np[side][b];
    if (cnt > CAPP) cnt = CAPP;
    ull T = radix_kth_largest(g_p1[side][b], cnt, need);
    for (int i = threadIdx.x; i < cnt; i += 256) {
        if (g_p1[side][b][i] >= T) {
            int pos = atomicAdd(&g_n[side][b], 1);
            if (pos < CAPC) g_rec[side][b][pos] = g_pr[side][b][i];
        }
    }
}

// P6: sparse exact top-K by Gumbel score with u-tier verification.
__global__ void __launch_bounds__(256) k_topk(const float* __restrict__ x) {
    __shared__ int s_cnt;
    __shared__ int s_done;
    int b = blockIdx.x, side = blockIdx.y;
    int K;
    if (side == 0) {
        int nf = g_nfg[b];
        K = g_deg[b] ? 0 : (nf < 100 ? nf : 100);
    } else {
        K = g_deg[b] ? 0 : 100;
    }
    if (K <= 0) return;
    int N = g_n[side][b];
    if (N > CAPC) N = CAPC;
    const ull* recs = g_rec[side][b];
    ull* sk = g_sk[side][b];
    const float* xb = x + (size_t)b * HWN;
    int tid = threadIdx.x;
    if (tid == 0) s_done = 0;
    __syncthreads();
    for (int tier = 0; tier < 3; tier++) {
        if (s_done) break;   // s_done only changes at barriers -> uniform
        u32 ucut = (tier == 0) ? UCUT0 : (tier == 1) ? UCUT1 : 0u;
        if (tid == 0) s_cnt = 0;
        __syncthreads();
        for (int i = tid; i < N; i += 256) {
            ull r = recs[i];
            u32 uhi = (u32)(r >> 32);
            if (uhi >= ucut) {
                float u = __uint_as_float(uhi & 0x7FFFFFFFu);
                int pix = (int)(r & 0xFFFFFFFFull);
                float v = xb[pix] + 1e-8f;
                float p = side ? (fmaxf(1.0f - v, 0.0f) + 1e-8f) : v;
                float s = logf(p) - logf(-logf(u));
                int pos = atomicAdd(&s_cnt, 1);
                sk[pos] = (((ull)fmono(s)) << 32) | (u32)(HWN - 1 - pix);
            }
        }
        __syncthreads();
        int cnt = s_cnt;
        bool ok = false;
        ull T = 0;
        if (cnt >= K) {
            T = radix_kth_largest(sk, cnt, K);
            if (tier == 2) ok = true;
            else {
                float sK = fmono_inv((u32)(T >> 32));
                float edge = (tier == 0) ? 0.984375f : 0.75f;
                float gc = -logf(-logf(edge));
                ok = (sK > gc);    // strict: excluded s <= g <= gc < sK
            }
        }
        if (ok) {
            ull* seed = g_seed[side][b];
            for (int i = tid; i < cnt; i += 256)
                if (sk[i] >= T) mark_seed(seed, HWN - 1 - (int)(sk[i] & 0xFFFFFFFFull));
            if (tid == 0) s_done = 1;
        }
        __syncthreads();
    }
}

// P7: 3x3 dilation + compose float32 output
__global__ void k_output(float* __restrict__ out) {
    __shared__ ull sv[2][8];
    __shared__ ull sh2[2][8];
    int t = blockIdx.x;
    int b = t >> 9;
    int row = t & 511;
    int c = threadIdx.x;
    if (c < 16) {
        int q = c >> 3, w = c & 7;
        const ull* seed = g_seed[q][b];
        ull v = seed[row * 8 + w];
        if (row > 0)      v |= seed[(row - 1) * 8 + w];
        if (row < HN - 1) v |= seed[(row + 1) * 8 + w];
        sv[q][w] = v;
    }
    __syncthreads();
    if (c < 16) {
        int q = c >> 3, w = c & 7;
        ull m = sv[q][w];
        ull hh = m | (m << 1) | (m >> 1);
        if (w > 0) hh |= sv[q][w - 1] >> 63;
        if (w < 7) hh |= sv[q][w + 1] << 63;
        sh2[q][w] = hh;
    }
    __syncthreads();
    int w = c >> 6, bit = c & 63;
    int f = (int)((sh2[0][w] >> bit) & 1ull);
    int g = (int)((sh2[1][w] >> bit) & 1ull);
    float val;
    if (f && !g)      val = 1.0f;
    else if (g && !f) val = 0.0f;
    else              val = -255.0f;
    out[(size_t)b * HWN + (size_t)row * WN + c] = val;
}

// ------------------------------ launch ------------------------------
extern "C" void kernel_launch(void* const* d_in, const int* in_sizes, int n_in,
                              void* d_out, int out_size) {
    (void)out_size;
    const float* big[3] = {nullptr, nullptr, nullptr};
    const float* rt = nullptr;
    int nb = 0;
    for (int i = 0; i < n_in && i < 4; i++) {
        if (in_sizes[i] == BN) rt = (const float*)d_in[i];
        else if (nb < 3)       big[nb++] = (const float*)d_in[i];
    }
    const float* x   = big[0];
    const float* ufg = big[1];
    const float* ubg = big[2];
    float* out = (float*)d_out;

    cudaFuncSetAttribute(k_erode, cudaFuncAttributeMaxDynamicSharedMemorySize, 65536);

    k_zero<<<512, 256>>>();
    k_prep<<<BN * 16, 256>>>(x, rt);
    k_erode<<<BN, 1024, 65536>>>();
    k_roihist<<<BN * 16, 256>>>(x);
    k_score<<<BN * 16, 256>>>(x, ufg, ubg);
    k_refine1<<<dim3(BN, 2), 256>>>();
    k_topk<<<dim3(BN, 2), 256>>>(x);
    k_output<<<BN * HN, 512>>>(out);
}